// round 4
// baseline (speedup 1.0000x reference)
#include <cuda_runtime.h>
#include <cuda_bf16.h>

// ResUpBlock (StyleGAN2-style): conv1(3x3)+FLReLU -> up2x -> conv2(3x3)+FLReLU,
// plus skip = conv1x1(up2x(x)); out = (main + skip)/sqrt(2).
//
// Decomposition:
//   K1: conv1 + fused leaky relu -> g_out1 [8,256,64,64]
//   K3: skip 1x1 conv on the 64x64 grid (commutes with upsample) -> g_skipy
//   K2: fused (bilinear-up of g_out1) * conv2 + leaky relu + (bilinear sample
//       of g_skipy) epilogue -> d_out. No upsampled tensor is materialized.
//
// Inner loops use Blackwell packed fp32 (fma.rn.f32x2 -> SASS FFMA2): each
// thread's 2 adjacent output columns form one f32x2 accumulator; weights are
// stored duplicated (w,w) in smem so the broadcast operand is one LDS.64.

#define N_BATCH 8
#define CIN 256
#define COUT 128
#define HS 64
#define WS 64
#define HL 128
#define WL 128

#define SQRT2F 1.4142135623730951f
#define INV_SQRT2F 0.7071067811865476f
#define SCALE3 (1.0f / 48.0f)   /* 1/sqrt(256*9) */
#define SCALE1 (1.0f / 16.0f)   /* 1/sqrt(256)   */

typedef unsigned long long u64t;

__device__ float g_out1[N_BATCH * CIN * HS * WS];    // 33.5 MB
__device__ float g_skipy[N_BATCH * COUT * HS * WS];  // 16.8 MB

__device__ __forceinline__ float flrelu(float v) {
    return (v >= 0.0f ? v : 0.2f * v) * SQRT2F;
}

// ---- packed fp32 helpers (sm_100+: fma.rn.f32x2) -------------------------
__device__ __forceinline__ u64t pk2(float lo, float hi) {
    u64t r;
    asm("mov.b64 %0, {%1, %2};" : "=l"(r) : "f"(lo), "f"(hi));
    return r;
}
__device__ __forceinline__ float2 upk2(u64t v) {
    float2 f;
    asm("mov.b64 {%0, %1}, %2;" : "=f"(f.x), "=f"(f.y) : "l"(v));
    return f;
}
__device__ __forceinline__ void fma2(u64t& d, u64t a, u64t b) {
    asm("fma.rn.f32x2 %0, %1, %2, %0;" : "+l"(d) : "l"(a), "l"(b));
}

// ---------------------------------------------------------------------------
// K1: conv3x3 (256->256, 64x64, pad=1) + bias + leaky relu -> g_out1
// Block: 128 threads, 32x32 spatial tile, 8 output channels.
// Thread: 4 rows x (1 col-pair) x 8 oc = 32 f32x2 accumulators.
// ---------------------------------------------------------------------------
#define K1_OC 8
#define K1_CI 4

__global__ void __launch_bounds__(128, 2)
conv1_kernel(const float* __restrict__ x, const float* __restrict__ w1,
             const float* __restrict__ b1) {
    __shared__ __align__(16) float s_in[K1_CI][34][36];
    __shared__ float2 s_w[K1_OC][K1_CI][9];

    const int tid = threadIdx.x;
    const int y0 = (blockIdx.x >> 1) * 32;
    const int x0 = (blockIdx.x & 1) * 32;
    const int ocg = blockIdx.y;      // 0..31
    const int n = blockIdx.z;

    const int tx = tid & 15;         // 16 col-pairs
    const int ty = tid >> 4;         // 8 row groups of 4
    const int r0 = ty * 4;
    const int c0 = tx * 2;

    u64t acc[K1_OC][4];
#pragma unroll
    for (int o = 0; o < K1_OC; o++)
#pragma unroll
        for (int s = 0; s < 4; s++) acc[o][s] = 0ull;

    const float* xin = x + (size_t)n * CIN * (HS * WS);

    for (int cb = 0; cb < CIN; cb += K1_CI) {
        // Load input tile 34x34 per ci (zero pad at image border).
        // 128 threads: thread handles (ci, r); 34*4=136 rows total.
        for (int t = tid; t < K1_CI * 34; t += 128) {
            int r = t % 34;
            int ci = t / 34;
            int gr = y0 - 1 + r;
            const float* rowp =
                xin + (size_t)(cb + ci) * (HS * WS) + gr * WS + (x0 - 1);
            float* srow = s_in[ci][r];
            if (gr >= 0 && gr < HS) {
#pragma unroll
                for (int c = 0; c < 34; c++) {
                    int gc = x0 - 1 + c;
                    srow[c] = (gc >= 0 && gc < WS) ? rowp[c] : 0.0f;
                }
            } else {
#pragma unroll
                for (int c = 0; c < 34; c++) srow[c] = 0.0f;
            }
        }
        // Load weights (scaled by 1/48) duplicated for packed broadcast.
        for (int idx = tid; idx < K1_OC * K1_CI * 9; idx += 128) {
            int kk = idx % 9;
            int t = idx / 9;
            int ci = t % K1_CI;
            int oc = t / K1_CI;
            float v =
                w1[((size_t)(ocg * K1_OC + oc) * CIN + (cb + ci)) * 9 + kk] * SCALE3;
            s_w[oc][ci][kk] = make_float2(v, v);
        }
        __syncthreads();

#pragma unroll
        for (int ci = 0; ci < K1_CI; ci++) {
            // Input pairs for the 3 kw shifts, 6 rows.
            u64t P0[6], P1[6], P2[6];
#pragma unroll
            for (int r = 0; r < 6; r++) {
                const float* rp = &s_in[ci][r0 + r][c0];
                u64t a = *(const u64t*)rp;        // (c0,   c0+1)
                u64t b = *(const u64t*)(rp + 2);  // (c0+2, c0+3)
                float2 fa = upk2(a), fb = upk2(b);
                P0[r] = a;
                P1[r] = pk2(fa.y, fb.x);          // (c0+1, c0+2)
                P2[r] = b;
            }
#pragma unroll
            for (int oc = 0; oc < K1_OC; oc++) {
                u64t w[9];
                const u64t* wp = (const u64t*)s_w[oc][ci];
#pragma unroll
                for (int k = 0; k < 9; k++) w[k] = wp[k];
#pragma unroll
                for (int ry = 0; ry < 4; ry++) {
                    u64t s = acc[oc][ry];
#pragma unroll
                    for (int kh = 0; kh < 3; kh++) {
                        fma2(s, P0[ry + kh], w[kh * 3 + 0]);
                        fma2(s, P1[ry + kh], w[kh * 3 + 1]);
                        fma2(s, P2[ry + kh], w[kh * 3 + 2]);
                    }
                    acc[oc][ry] = s;
                }
            }
        }
        __syncthreads();
    }

#pragma unroll
    for (int oc = 0; oc < K1_OC; oc++) {
        int goc = ocg * K1_OC + oc;
        float bias = b1[goc];
        float* op = g_out1 + ((size_t)n * CIN + goc) * (HS * WS);
#pragma unroll
        for (int ry = 0; ry < 4; ry++) {
            float2 v = upk2(acc[oc][ry]);
            float2 r = make_float2(flrelu(v.x + bias), flrelu(v.y + bias));
            *(float2*)&op[(y0 + r0 + ry) * WS + (x0 + c0)] = r;
        }
    }
}

// ---------------------------------------------------------------------------
// K3: skip = 1x1 equalized conv on the ORIGINAL 64x64 grid (upsample commutes
// with 1x1 conv; the upsample happens in K2's epilogue).
// ---------------------------------------------------------------------------
__global__ void __launch_bounds__(256)
skip_kernel(const float* __restrict__ x, const float* __restrict__ wsk) {
    __shared__ float s_w[16][CIN];
    const int tid = threadIdx.x;
    const int ocg = blockIdx.y;  // 0..7 (8 groups of 16 oc)

    for (int idx = tid; idx < 16 * CIN; idx += 256) {
        int oc = idx / CIN;
        int ci = idx % CIN;
        s_w[oc][ci] = wsk[(size_t)(ocg * 16 + oc) * CIN + ci] * SCALE1;
    }
    __syncthreads();

    const int pos = blockIdx.x * 256 + tid;          // 0 .. 8*4096-1
    const int n = pos >> 12;
    const int hw = pos & 4095;
    const float* xp = x + (size_t)n * CIN * (HS * WS) + hw;

    float acc[16];
#pragma unroll
    for (int oc = 0; oc < 16; oc++) acc[oc] = 0.0f;

#pragma unroll 8
    for (int ci = 0; ci < CIN; ci++) {
        float v = xp[(size_t)ci * (HS * WS)];
#pragma unroll
        for (int oc = 0; oc < 16; oc++) acc[oc] += v * s_w[oc][ci];
    }

    float* yp = g_skipy + (size_t)n * COUT * (HS * WS) +
                (size_t)(ocg * 16) * (HS * WS) + hw;
#pragma unroll
    for (int oc = 0; oc < 16; oc++) yp[(size_t)oc * (HS * WS)] = acc[oc];
}

// ---------------------------------------------------------------------------
// K2: fused [bilinear up 2x of g_out1] -> conv3x3 (256->128, pad=1) + bias +
// leaky relu + [bilinear sample of g_skipy] epilogue -> d_out, all /sqrt(2).
//
// Bilinear (half-pixel, scale 2): out coord u samples src i=u>>1 with weight
// 0.75 and j=i-1 (u even) / i+1 (u odd) with weight 0.25, indices clamped.
// ---------------------------------------------------------------------------
#define K2_OC 8
#define K2_CI 4

__global__ void __launch_bounds__(128, 2)
conv2_kernel(const float* __restrict__ w2, const float* __restrict__ b2,
             float* __restrict__ out) {
    __shared__ __align__(16) float s_src[K2_CI][18][20];
    __shared__ __align__(16) float s_up[K2_CI][34][36];
    __shared__ float2 s_w[K2_OC][K2_CI][9];

    const int tid = threadIdx.x;
    const int oy0 = (blockIdx.x >> 2) * 32;
    const int ox0 = (blockIdx.x & 3) * 32;
    const int ocg = blockIdx.y;  // 0..15
    const int n = blockIdx.z;

    const int sy0 = oy0 / 2 - 1;
    const int sx0 = ox0 / 2 - 1;

    const int tx = tid & 15;
    const int ty = tid >> 4;
    const int r0 = ty * 4;
    const int c0 = tx * 2;

    u64t acc[K2_OC][4];
#pragma unroll
    for (int o = 0; o < K2_OC; o++)
#pragma unroll
        for (int s = 0; s < 4; s++) acc[o][s] = 0ull;

    const float* src = g_out1 + (size_t)n * CIN * (HS * WS);

    for (int cb = 0; cb < CIN; cb += K2_CI) {
        // Phase 1: load 18x18 source tile per ci (clamped indices).
        for (int idx = tid; idx < K2_CI * 18 * 18; idx += 128) {
            int c = idx % 18;
            int t = idx / 18;
            int r = t % 18;
            int ci = t / 18;
            int gr = min(max(sy0 + r, 0), HS - 1);
            int gc = min(max(sx0 + c, 0), WS - 1);
            s_src[ci][r][c] = src[(size_t)(cb + ci) * (HS * WS) + gr * WS + gc];
        }
        for (int idx = tid; idx < K2_OC * K2_CI * 9; idx += 128) {
            int kk = idx % 9;
            int t = idx / 9;
            int ci = t % K2_CI;
            int oc = t / K2_CI;
            float v =
                w2[((size_t)(ocg * K2_OC + oc) * CIN + (cb + ci)) * 9 + kk] * SCALE3;
            s_w[oc][ci][kk] = make_float2(v, v);
        }
        __syncthreads();

        // Phase 2: expand to 34x34 upsampled tile (zero outside 128x128 = pad).
        for (int idx = tid; idx < K2_CI * 34 * 34; idx += 128) {
            int c = idx % 34;
            int t = idx / 34;
            int r = t % 34;
            int ci = t / 34;
            int uy = oy0 - 1 + r;
            int ux = ox0 - 1 + c;
            float v = 0.0f;
            if (uy >= 0 && uy < HL && ux >= 0 && ux < WL) {
                int iy = uy >> 1;
                int jy = (uy & 1) ? iy + 1 : iy - 1;
                int ix = ux >> 1;
                int jx = (ux & 1) ? ix + 1 : ix - 1;
                jy = min(max(jy, 0), HS - 1);
                jx = min(max(jx, 0), WS - 1);
                int liy = iy - sy0, ljy = jy - sy0;
                int lix = ix - sx0, ljx = jx - sx0;
                v = 0.5625f * s_src[ci][liy][lix] +
                    0.1875f * (s_src[ci][liy][ljx] + s_src[ci][ljy][lix]) +
                    0.0625f * s_src[ci][ljy][ljx];
            }
            s_up[ci][r][c] = v;
        }
        __syncthreads();

        // Phase 3: packed 3x3 conv over the upsampled tile.
#pragma unroll
        for (int ci = 0; ci < K2_CI; ci++) {
            u64t P0[6], P1[6], P2[6];
#pragma unroll
            for (int r = 0; r < 6; r++) {
                const float* rp = &s_up[ci][r0 + r][c0];
                u64t a = *(const u64t*)rp;
                u64t b = *(const u64t*)(rp + 2);
                float2 fa = upk2(a), fb = upk2(b);
                P0[r] = a;
                P1[r] = pk2(fa.y, fb.x);
                P2[r] = b;
            }
#pragma unroll
            for (int oc = 0; oc < K2_OC; oc++) {
                u64t w[9];
                const u64t* wp = (const u64t*)s_w[oc][ci];
#pragma unroll
                for (int k = 0; k < 9; k++) w[k] = wp[k];
#pragma unroll
                for (int ry = 0; ry < 4; ry++) {
                    u64t s = acc[oc][ry];
#pragma unroll
                    for (int kh = 0; kh < 3; kh++) {
                        fma2(s, P0[ry + kh], w[kh * 3 + 0]);
                        fma2(s, P1[ry + kh], w[kh * 3 + 1]);
                        fma2(s, P2[ry + kh], w[kh * 3 + 2]);
                    }
                    acc[oc][ry] = s;
                }
            }
        }
        __syncthreads();
    }

    // Epilogue: activation + bilinear-sampled skip + final scale.
#pragma unroll
    for (int oc = 0; oc < K2_OC; oc++) {
        int goc = ocg * K2_OC + oc;
        float bias = b2[goc];
        const float* sy = g_skipy + ((size_t)n * COUT + goc) * (HS * WS);
        float* op = out + ((size_t)n * COUT + goc) * (HL * WL);
#pragma unroll
        for (int ry = 0; ry < 4; ry++) {
            int oh = oy0 + r0 + ry;
            int iy = oh >> 1;
            int jy = (oh & 1) ? min(iy + 1, HS - 1) : max(iy - 1, 0);
            float2 v = upk2(acc[oc][ry]);
            float vv[2] = {v.x, v.y};
#pragma unroll
            for (int rx = 0; rx < 2; rx++) {
                int ow = ox0 + c0 + rx;
                int ix = ow >> 1;
                int jx = (ow & 1) ? min(ix + 1, WS - 1) : max(ix - 1, 0);
                float skip = 0.5625f * sy[iy * WS + ix] +
                             0.1875f * (sy[iy * WS + jx] + sy[jy * WS + ix]) +
                             0.0625f * sy[jy * WS + jx];
                float m = flrelu(vv[rx] + bias);
                op[oh * WL + ow] = (m + skip) * INV_SQRT2F;
            }
        }
    }
}

// ---------------------------------------------------------------------------
extern "C" void kernel_launch(void* const* d_in, const int* in_sizes, int n_in,
                              void* d_out, int out_size) {
    const float* x = (const float*)d_in[0];
    const float* w1 = (const float*)d_in[1];
    const float* b1 = (const float*)d_in[2];
    const float* w2 = (const float*)d_in[3];
    const float* b2 = (const float*)d_in[4];
    const float* wsk = (const float*)d_in[5];
    float* out = (float*)d_out;

    // K1: conv1 -> g_out1
    conv1_kernel<<<dim3(4, CIN / K1_OC, N_BATCH), 128>>>(x, w1, b1);
    // K3: skip 1x1 on 64x64 grid -> g_skipy (independent of K1)
    skip_kernel<<<dim3((N_BATCH * HS * WS) / 256, COUT / 16), 256>>>(x, wsk);
    // K2: fused up+conv2+act+skip -> d_out
    conv2_kernel<<<dim3(16, COUT / K2_OC, N_BATCH), 128>>>(w2, b2, out);
}